// round 8
// baseline (speedup 1.0000x reference)
#include <cuda_runtime.h>
#include <cuda_bf16.h>
#include <cstdint>

// Problem dims
#define NI 16384
#define NC 4096
#define ND 256
#define KK 512              // fused GEMM K (elements)

// Tiling
#define BM 128
#define BN 256
#define BK 64               // bf16 elems per k-chunk = 128 bytes/row
#define KITERS (KK / BK)    // 8
#define NSTAGE 2
#define CHUNKB 128          // bytes per row per chunk

#define A_TILE_BYTES (BM * CHUNKB)       // 16384
#define B_TILE_BYTES (BN * CHUNKB)       // 32768
#define STAGE_BYTES (A_TILE_BYTES + B_TILE_BYTES)   // 49152
#define SM_A(st) (1024 + (st) * STAGE_BYTES)
#define SM_B(st) (SM_A(st) + A_TILE_BYTES)
#define SMEM_BYTES (1024 + NSTAGE * STAGE_BYTES)    // 99328

// Device scratch, k-chunk-major with SW128 swizzle baked in:
// byte addr = ((kchunk*ROWS + row)*128) + (2*e ^ ((row&7)<<4))
__device__ uint8_t g_A[(size_t)KITERS * NI * CHUNKB];   // 16.8 MB
__device__ uint8_t g_B[(size_t)KITERS * NC * CHUNKB];   //  4.2 MB
__device__ float g_csum[NC];
__device__ float g_score[NI];

// ---------------------------------------------------------------- helpers
__device__ __forceinline__ uint32_t smem_u32(const void* p) {
    uint32_t a;
    asm("{ .reg .u64 t; cvta.to.shared.u64 t, %1; cvt.u32.u64 %0, t; }" : "=r"(a) : "l"(p));
    return a;
}
#define MBAR_INIT(a, n) \
    asm volatile("mbarrier.init.shared.b64 [%0], %1;" :: "r"(a), "r"(n) : "memory")
#define MBAR_EXPECT_TX(a, bytes) \
    asm volatile("mbarrier.arrive.expect_tx.shared.b64 _, [%0], %1;" :: "r"(a), "r"(bytes) : "memory")
#define MBAR_WAIT(a, ph) do {                                                     \
    uint32_t _m = (a), _p = (ph), _d;                                             \
    asm volatile("{ .reg .pred p; mbarrier.try_wait.parity.acquire.cta.shared::cta.b64 p, [%1], %2; selp.b32 %0,1,0,p; }" \
                 : "=r"(_d) : "r"(_m), "r"(_p) : "memory");                       \
    if (!_d) {                                                                    \
        asm volatile("{ .reg .pred P; W%=: mbarrier.try_wait.parity.acquire.cta.shared::cta.b64 P, [%0], %1, 0x989680; @P bra.uni D%=; bra.uni W%=; D%=: }" \
                     :: "r"(_m), "r"(_p) : "memory");                             \
    } } while (0)
#define CP_BULK(dst, src, bytes, mbar) \
    asm volatile("cp.async.bulk.shared::cluster.global.mbarrier::complete_tx::bytes " \
                 "[%0], [%1], %2, [%3];" \
                 :: "r"(dst), "l"(src), "r"(bytes), "r"(mbar) : "memory")

__device__ __forceinline__ void ldm_x4(uint32_t* r, uint32_t addr) {
    asm volatile("ldmatrix.sync.aligned.m8n8.x4.shared.b16 {%0,%1,%2,%3}, [%4];"
                 : "=r"(r[0]), "=r"(r[1]), "=r"(r[2]), "=r"(r[3]) : "r"(addr));
}
__device__ __forceinline__ void mma_bf16(float* c, const uint32_t* a, const uint32_t* b) {
    asm volatile(
        "mma.sync.aligned.m16n8k16.row.col.f32.bf16.bf16.f32 "
        "{%0,%1,%2,%3}, {%4,%5,%6,%7}, {%8,%9}, {%0,%1,%2,%3};"
        : "+f"(c[0]), "+f"(c[1]), "+f"(c[2]), "+f"(c[3])
        : "r"(a[0]), "r"(a[1]), "r"(a[2]), "r"(a[3]), "r"(b[0]), "r"(b[1]));
}

// ---------------------------------------------------------------- prep kernels
__global__ void prep_A_kernel(const float* __restrict__ x) {
    int idx = blockIdx.x * blockDim.x + threadIdx.x;
    if (idx >= NI * ND) return;
    int n = idx >> 8;
    int d = idx & (ND - 1);
    float v = x[idx];
    uint32_t sw = ((uint32_t)(n & 7)) << 4;
    int kch_sq = d >> 6, e = d & 63;
    *(__nv_bfloat16*)(g_A + ((size_t)kch_sq * NI + n) * CHUNKB + ((2 * e) ^ sw)) =
        __float2bfloat16(v * v);
    *(__nv_bfloat16*)(g_A + ((size_t)(4 + kch_sq) * NI + n) * CHUNKB + ((2 * e) ^ sw)) =
        __float2bfloat16(v);
}

__global__ void prep_B_kernel(const float* __restrict__ centers,
                              const float* __restrict__ sigmas) {
    int warp = (blockIdx.x * blockDim.x + threadIdx.x) >> 5;
    int lane = threadIdx.x & 31;
    if (warp >= NC) return;
    int c = warp;
    uint32_t sw = ((uint32_t)(c & 7)) << 4;
    float acc = 0.f;
    #pragma unroll
    for (int d = lane; d < ND; d += 32) {
        float s   = sigmas[c * ND + d];
        float ce  = centers[c * ND + d];
        float inv = 1.0f / (2.0f * s * s);
        int kch = d >> 6, e = d & 63;
        *(__nv_bfloat16*)(g_B + ((size_t)kch * NC + c) * CHUNKB + ((2 * e) ^ sw)) =
            __float2bfloat16(inv);
        *(__nv_bfloat16*)(g_B + ((size_t)(4 + kch) * NC + c) * CHUNKB + ((2 * e) ^ sw)) =
            __float2bfloat16(-2.0f * ce * inv);
        acc = fmaf(ce * ce, inv, acc);
    }
    #pragma unroll
    for (int m = 16; m; m >>= 1) acc += __shfl_xor_sync(0xffffffffu, acc, m);
    if (lane == 0) g_csum[c] = acc;
}

__global__ void zero_score_kernel() {
    int i = blockIdx.x * blockDim.x + threadIdx.x;
    if (i < NI) g_score[i] = 0.f;
}

// ---------------------------------------------------------------- main kernel
__global__ void __launch_bounds__(256, 2)
rbf_mma_kernel(const float* __restrict__ w_lin) {
    extern __shared__ char smem[];
    const uint32_t smem_base = smem_u32(smem);
    const int tid  = threadIdx.x;
    const int lane = tid & 31;
    const int wid  = tid >> 5;
    const int wm   = wid >> 2;      // 0..1  (M: 64 rows each)
    const int wn   = wid & 3;       // 0..3  (N: 64 cols each)
    const int bn   = blockIdx.x;    // center tile (16)
    const int bm   = blockIdx.y;    // input tile  (128)

    if (tid == 0) {
        MBAR_INIT(smem_base + 0, 1);
        MBAR_INIT(smem_base + 8, 1);
    }
    __syncthreads();

    auto issue_stage = [&](int st, int kiter) {
        uint32_t mb = smem_base + st * 8;
        MBAR_EXPECT_TX(mb, STAGE_BYTES);
        const uint8_t* srcA = g_A + ((size_t)kiter * NI + bm * BM) * CHUNKB;
        const uint8_t* srcB = g_B + ((size_t)kiter * NC + bn * BN) * CHUNKB;
        CP_BULK(smem_base + SM_A(st), (const void*)srcA, A_TILE_BYTES, mb);
        CP_BULK(smem_base + SM_B(st), (const void*)srcB, B_TILE_BYTES, mb);
    };

    if (tid == 0) {
        issue_stage(0, 0);
        issue_stage(1, 1);
    }

    float acc[4][8][4];
    #pragma unroll
    for (int mt = 0; mt < 4; mt++)
        #pragma unroll
        for (int nt = 0; nt < 8; nt++)
            #pragma unroll
            for (int e = 0; e < 4; e++) acc[mt][nt][e] = 0.f;

    #pragma unroll 1
    for (int k = 0; k < KITERS; k++) {
        const int st = k & 1;
        MBAR_WAIT(smem_base + st * 8, (k >> 1) & 1);

        const uint32_t aBase = smem_base + SM_A(st);
        const uint32_t bBase = smem_base + SM_B(st);
        #pragma unroll
        for (int kc = 0; kc < 4; kc++) {           // 4 x k16 per stage
            uint32_t a[4][4], b[8][2];
            #pragma unroll
            for (int mt = 0; mt < 4; mt++) {
                int row = wm * 64 + mt * 16 + (lane & 15);
                uint32_t boff = kc * 32 + ((lane >> 4) << 4);
                uint32_t addr = aBase + row * CHUNKB + (boff ^ ((row & 7) << 4));
                ldm_x4(a[mt], addr);
            }
            // B: 4 merged x4 loads; each covers two n8-tiles (k0+k8 fragments)
            #pragma unroll
            for (int p = 0; p < 4; p++) {
                int g = lane >> 3;            // 0..3: {t0 k0, t0 k8, t1 k0, t1 k8}
                int trow = wn * 64 + p * 16 + (g >> 1) * 8 + (lane & 7);
                uint32_t boff = kc * 32 + ((g & 1) << 4);
                uint32_t addr = bBase + trow * CHUNKB + (boff ^ ((trow & 7) << 4));
                uint32_t bp[4];
                ldm_x4(bp, addr);
                b[2 * p][0] = bp[0]; b[2 * p][1] = bp[1];
                b[2 * p + 1][0] = bp[2]; b[2 * p + 1][1] = bp[3];
            }
            #pragma unroll
            for (int mt = 0; mt < 4; mt++)
                #pragma unroll
                for (int nt = 0; nt < 8; nt++)
                    mma_bf16(acc[mt][nt], a[mt], b[nt]);
        }

        // all warps done reading stage st -> safe to refill it with k+2
        __syncthreads();
        if (tid == 0 && k + NSTAGE < KITERS) issue_stage(st, k + NSTAGE);
    }

    // ---------------- epilogue: d2 = acc + csum; add exp(-d2)*w only if d2<60
    const int cBase = bn * BN + wn * 64;
    float cs[8][2], wv[8][2];
    #pragma unroll
    for (int nt = 0; nt < 8; nt++)
        #pragma unroll
        for (int j = 0; j < 2; j++) {
            int c = cBase + nt * 8 + (lane & 3) * 2 + j;
            cs[nt][j] = __ldg(&g_csum[c]);
            wv[nt][j] = __ldg(&w_lin[c]);
        }

    float mn = 1e30f;
    #pragma unroll
    for (int mt = 0; mt < 4; mt++)
        #pragma unroll
        for (int nt = 0; nt < 8; nt++)
            #pragma unroll
            for (int e = 0; e < 4; e++)
                mn = fminf(mn, acc[mt][nt][e] + cs[nt][e & 1]);

    if (__any_sync(0xffffffffu, mn < 60.f)) {       // rare path
        float rs[4][2];
        #pragma unroll
        for (int mt = 0; mt < 4; mt++) { rs[mt][0] = 0.f; rs[mt][1] = 0.f; }
        #pragma unroll
        for (int mt = 0; mt < 4; mt++)
            #pragma unroll
            for (int nt = 0; nt < 8; nt++)
                #pragma unroll
                for (int e = 0; e < 4; e++) {
                    float d2 = acc[mt][nt][e] + cs[nt][e & 1];
                    if (d2 < 60.f)
                        rs[mt][e >> 1] = fmaf(__expf(-d2), wv[nt][e & 1], rs[mt][e >> 1]);
                }
        #pragma unroll
        for (int mt = 0; mt < 4; mt++)
            #pragma unroll
            for (int h = 0; h < 2; h++) {
                float v = rs[mt][h];
                v += __shfl_xor_sync(0xffffffffu, v, 1);
                v += __shfl_xor_sync(0xffffffffu, v, 2);
                if ((lane & 3) == 0)
                    atomicAdd(&g_score[bm * BM + wm * 64 + mt * 16 + h * 8 + (lane >> 2)], v);
            }
    }
    // fast path: contributions are 0; g_score pre-zeroed -> nothing to do
}

__global__ void finalize_kernel(const float* __restrict__ b_lin,
                                float* __restrict__ out) {
    int n = blockIdx.x * blockDim.x + threadIdx.x;
    if (n < NI) {
        float s = g_score[n] + b_lin[0];
        out[n] = 1.0f / (1.0f + __expf(-s));
    }
}

// ---------------------------------------------------------------- launch
extern "C" void kernel_launch(void* const* d_in, const int* in_sizes, int n_in,
                              void* d_out, int out_size) {
    const float* x       = (const float*)d_in[0];
    const float* centers = (const float*)d_in[1];
    const float* sigmas  = (const float*)d_in[2];
    const float* w_lin   = (const float*)d_in[3];
    const float* b_lin   = (const float*)d_in[4];
    float* out = (float*)d_out;

    cudaFuncSetAttribute(rbf_mma_kernel,
                         cudaFuncAttributeMaxDynamicSharedMemorySize, SMEM_BYTES);

    prep_A_kernel<<<(NI * ND + 255) / 256, 256>>>(x);
    prep_B_kernel<<<(NC * 32 + 255) / 256, 256>>>(centers, sigmas);
    zero_score_kernel<<<NI / 256, 256>>>();
    dim3 grid(NC / BN, NI / BM);   // (16, 128)
    rbf_mma_kernel<<<grid, 256, SMEM_BYTES>>>(w_lin);
    finalize_kernel<<<NI / 256, 256>>>(b_lin, out);
}

// round 9
// speedup vs baseline: 3.1978x; 3.1978x over previous
#include <cuda_runtime.h>
#include <cuda_bf16.h>
#include <cstdint>

// Problem dims
#define NI 16384
#define NC 4096
#define ND 256
#define KK 512              // fused GEMM K (elements)

// Tiling
#define BM 128
#define BN 128
#define BK 64               // bf16 elems per k-chunk = 128 bytes/row
#define KITERS (KK / BK)    // 8
#define NSTAGE 3
#define CHUNKB 128          // bytes per row per chunk

#define A_TILE_BYTES (BM * CHUNKB)       // 16384
#define B_TILE_BYTES (BN * CHUNKB)       // 16384
#define STAGE_BYTES (A_TILE_BYTES + B_TILE_BYTES)   // 32768
#define SM_A(st) (1024 + (st) * STAGE_BYTES)
#define SM_B(st) (SM_A(st) + A_TILE_BYTES)
#define SMEM_BYTES (1024 + NSTAGE * STAGE_BYTES)    // 99328

// Device scratch, k-chunk-major with SW128 swizzle baked in:
// byte addr = ((kchunk*ROWS + row)*128) + (2*e ^ ((row&7)<<4))
__device__ uint8_t g_A[(size_t)KITERS * NI * CHUNKB];   // 16.8 MB
__device__ uint8_t g_B[(size_t)KITERS * NC * CHUNKB];   //  4.2 MB
__device__ float g_csum[NC];
__device__ float g_score[NI];

// ---------------------------------------------------------------- helpers
__device__ __forceinline__ uint32_t smem_u32(const void* p) {
    uint32_t a;
    asm("{ .reg .u64 t; cvta.to.shared.u64 t, %1; cvt.u32.u64 %0, t; }" : "=r"(a) : "l"(p));
    return a;
}
#define MBAR_INIT(a, n) \
    asm volatile("mbarrier.init.shared.b64 [%0], %1;" :: "r"(a), "r"(n) : "memory")
#define MBAR_EXPECT_TX(a, bytes) \
    asm volatile("mbarrier.arrive.expect_tx.shared.b64 _, [%0], %1;" :: "r"(a), "r"(bytes) : "memory")
#define MBAR_WAIT(a, ph) do {                                                     \
    uint32_t _m = (a), _p = (ph), _d;                                             \
    asm volatile("{ .reg .pred p; mbarrier.try_wait.parity.acquire.cta.shared::cta.b64 p, [%1], %2; selp.b32 %0,1,0,p; }" \
                 : "=r"(_d) : "r"(_m), "r"(_p) : "memory");                       \
    if (!_d) {                                                                    \
        asm volatile("{ .reg .pred P; W%=: mbarrier.try_wait.parity.acquire.cta.shared::cta.b64 P, [%0], %1, 0x989680; @P bra.uni D%=; bra.uni W%=; D%=: }" \
                     :: "r"(_m), "r"(_p) : "memory");                             \
    } } while (0)
#define CP_BULK(dst, src, bytes, mbar) \
    asm volatile("cp.async.bulk.shared::cluster.global.mbarrier::complete_tx::bytes " \
                 "[%0], [%1], %2, [%3];" \
                 :: "r"(dst), "l"(src), "r"(bytes), "r"(mbar) : "memory")

__device__ __forceinline__ void ldm_x4(uint32_t* r, uint32_t addr) {
    asm volatile("ldmatrix.sync.aligned.m8n8.x4.shared.b16 {%0,%1,%2,%3}, [%4];"
                 : "=r"(r[0]), "=r"(r[1]), "=r"(r[2]), "=r"(r[3]) : "r"(addr));
}
__device__ __forceinline__ void mma_bf16(float* c, const uint32_t* a, const uint32_t* b) {
    asm volatile(
        "mma.sync.aligned.m16n8k16.row.col.f32.bf16.bf16.f32 "
        "{%0,%1,%2,%3}, {%4,%5,%6,%7}, {%8,%9}, {%0,%1,%2,%3};"
        : "+f"(c[0]), "+f"(c[1]), "+f"(c[2]), "+f"(c[3])
        : "r"(a[0]), "r"(a[1]), "r"(a[2]), "r"(a[3]), "r"(b[0]), "r"(b[1]));
}

// ---------------------------------------------------------------- prep kernels
__global__ void prep_A_kernel(const float* __restrict__ x) {
    int idx = blockIdx.x * blockDim.x + threadIdx.x;
    if (idx >= NI * ND) return;
    if (idx < NI) g_score[idx] = 0.f;        // fold score zeroing in
    int n = idx >> 8;
    int d = idx & (ND - 1);
    float v = x[idx];
    uint32_t sw = ((uint32_t)(n & 7)) << 4;
    int kch_sq = d >> 6, e = d & 63;
    *(__nv_bfloat16*)(g_A + ((size_t)kch_sq * NI + n) * CHUNKB + ((2 * e) ^ sw)) =
        __float2bfloat16(v * v);
    *(__nv_bfloat16*)(g_A + ((size_t)(4 + kch_sq) * NI + n) * CHUNKB + ((2 * e) ^ sw)) =
        __float2bfloat16(v);
}

__global__ void prep_B_kernel(const float* __restrict__ centers,
                              const float* __restrict__ sigmas) {
    int warp = (blockIdx.x * blockDim.x + threadIdx.x) >> 5;
    int lane = threadIdx.x & 31;
    if (warp >= NC) return;
    int c = warp;
    uint32_t sw = ((uint32_t)(c & 7)) << 4;
    float acc = 0.f;
    #pragma unroll
    for (int d = lane; d < ND; d += 32) {
        float s   = sigmas[c * ND + d];
        float ce  = centers[c * ND + d];
        float inv = 1.0f / (2.0f * s * s);
        int kch = d >> 6, e = d & 63;
        *(__nv_bfloat16*)(g_B + ((size_t)kch * NC + c) * CHUNKB + ((2 * e) ^ sw)) =
            __float2bfloat16(inv);
        *(__nv_bfloat16*)(g_B + ((size_t)(4 + kch) * NC + c) * CHUNKB + ((2 * e) ^ sw)) =
            __float2bfloat16(-2.0f * ce * inv);
        acc = fmaf(ce * ce, inv, acc);
    }
    #pragma unroll
    for (int m = 16; m; m >>= 1) acc += __shfl_xor_sync(0xffffffffu, acc, m);
    if (lane == 0) g_csum[c] = acc;
}

// ---------------------------------------------------------------- main kernel
__global__ void __launch_bounds__(256, 2)
rbf_mma_kernel(const float* __restrict__ w_lin) {
    extern __shared__ char smem[];
    const uint32_t smem_base = smem_u32(smem);
    const int tid  = threadIdx.x;
    const int lane = tid & 31;
    const int wid  = tid >> 5;
    const int wm   = wid >> 2;      // 0..1  (M)
    const int wn   = wid & 3;       // 0..3  (N)
    const int bn   = blockIdx.x;    // center tile
    const int bm   = blockIdx.y;    // input tile

    if (tid == 0) {
        MBAR_INIT(smem_base + 0, 1);
        MBAR_INIT(smem_base + 8, 1);
        MBAR_INIT(smem_base + 16, 1);
    }
    __syncthreads();

    auto issue_stage = [&](int st, int kiter) {
        uint32_t mb = smem_base + st * 8;
        MBAR_EXPECT_TX(mb, STAGE_BYTES);
        const uint8_t* srcA = g_A + ((size_t)kiter * NI + bm * BM) * CHUNKB;
        const uint8_t* srcB = g_B + ((size_t)kiter * NC + bn * BN) * CHUNKB;
        CP_BULK(smem_base + SM_A(st), (const void*)srcA, A_TILE_BYTES, mb);
        CP_BULK(smem_base + SM_B(st), (const void*)srcB, B_TILE_BYTES, mb);
    };

    if (tid == 0) {
        issue_stage(0, 0);
        issue_stage(1, 1);
        issue_stage(2, 2);
    }

    float acc[4][4][4];
    #pragma unroll
    for (int mt = 0; mt < 4; mt++)
        #pragma unroll
        for (int nt = 0; nt < 4; nt++)
            #pragma unroll
            for (int e = 0; e < 4; e++) acc[mt][nt][e] = 0.f;

    #pragma unroll 1
    for (int k = 0; k < KITERS; k++) {
        const int st = k % NSTAGE;
        MBAR_WAIT(smem_base + st * 8, (k / NSTAGE) & 1);

        const uint32_t aBase = smem_base + SM_A(st);
        const uint32_t bBase = smem_base + SM_B(st);
        #pragma unroll
        for (int kc = 0; kc < 4; kc++) {           // 4 x k16 per stage
            uint32_t a[4][4], b[4][2];
            #pragma unroll
            for (int mt = 0; mt < 4; mt++) {
                int row = wm * 64 + mt * 16 + (lane & 15);
                uint32_t boff = kc * 32 + ((lane >> 4) << 4);
                uint32_t addr = aBase + row * CHUNKB + (boff ^ ((row & 7) << 4));
                ldm_x4(a[mt], addr);
            }
            // B: 2 merged x4 loads; each covers two n8-tiles (k0+k8 fragments)
            #pragma unroll
            for (int p = 0; p < 2; p++) {
                int g = lane >> 3;            // 0..3: {t0 k0, t0 k8, t1 k0, t1 k8}
                int trow = wn * 32 + p * 16 + (g >> 1) * 8 + (lane & 7);
                uint32_t boff = kc * 32 + ((g & 1) << 4);
                uint32_t addr = bBase + trow * CHUNKB + (boff ^ ((trow & 7) << 4));
                uint32_t bp[4];
                ldm_x4(bp, addr);
                b[2 * p][0] = bp[0]; b[2 * p][1] = bp[1];
                b[2 * p + 1][0] = bp[2]; b[2 * p + 1][1] = bp[3];
            }
            #pragma unroll
            for (int mt = 0; mt < 4; mt++)
                #pragma unroll
                for (int nt = 0; nt < 4; nt++)
                    mma_bf16(acc[mt][nt], a[mt], b[nt]);
        }

        // all warps done reading stage st -> safe to refill it with k+3
        __syncthreads();
        if (tid == 0 && k + NSTAGE < KITERS) issue_stage(st, k + NSTAGE);
    }

    // ---------------- epilogue: d2 = acc + csum; add exp(-d2)*w only if d2<60
    const int cBase = bn * BN + wn * 32;
    float cs[4][2], wv[4][2];
    #pragma unroll
    for (int nt = 0; nt < 4; nt++)
        #pragma unroll
        for (int j = 0; j < 2; j++) {
            int c = cBase + nt * 8 + (lane & 3) * 2 + j;
            cs[nt][j] = __ldg(&g_csum[c]);
            wv[nt][j] = __ldg(&w_lin[c]);
        }

    float mn = 1e30f;
    #pragma unroll
    for (int mt = 0; mt < 4; mt++)
        #pragma unroll
        for (int nt = 0; nt < 4; nt++)
            #pragma unroll
            for (int e = 0; e < 4; e++)
                mn = fminf(mn, acc[mt][nt][e] + cs[nt][e & 1]);

    if (__any_sync(0xffffffffu, mn < 60.f)) {       // rare path
        float rs[4][2];
        #pragma unroll
        for (int mt = 0; mt < 4; mt++) { rs[mt][0] = 0.f; rs[mt][1] = 0.f; }
        #pragma unroll
        for (int mt = 0; mt < 4; mt++)
            #pragma unroll
            for (int nt = 0; nt < 4; nt++)
                #pragma unroll
                for (int e = 0; e < 4; e++) {
                    float d2 = acc[mt][nt][e] + cs[nt][e & 1];
                    if (d2 < 60.f)
                        rs[mt][e >> 1] = fmaf(__expf(-d2), wv[nt][e & 1], rs[mt][e >> 1]);
                }
        #pragma unroll
        for (int mt = 0; mt < 4; mt++)
            #pragma unroll
            for (int h = 0; h < 2; h++) {
                float v = rs[mt][h];
                v += __shfl_xor_sync(0xffffffffu, v, 1);
                v += __shfl_xor_sync(0xffffffffu, v, 2);
                if ((lane & 3) == 0)
                    atomicAdd(&g_score[bm * BM + wm * 64 + mt * 16 + h * 8 + (lane >> 2)], v);
            }
    }
    // fast path: contributions are 0; g_score pre-zeroed -> nothing to do
}

__global__ void finalize_kernel(const float* __restrict__ b_lin,
                                float* __restrict__ out) {
    int n = blockIdx.x * blockDim.x + threadIdx.x;
    if (n < NI) {
        float s = g_score[n] + b_lin[0];
        out[n] = 1.0f / (1.0f + __expf(-s));
    }
}

// ---------------------------------------------------------------- launch
extern "C" void kernel_launch(void* const* d_in, const int* in_sizes, int n_in,
                              void* d_out, int out_size) {
    const float* x       = (const float*)d_in[0];
    const float* centers = (const float*)d_in[1];
    const float* sigmas  = (const float*)d_in[2];
    const float* w_lin   = (const float*)d_in[3];
    const float* b_lin   = (const float*)d_in[4];
    float* out = (float*)d_out;

    cudaFuncSetAttribute(rbf_mma_kernel,
                         cudaFuncAttributeMaxDynamicSharedMemorySize, SMEM_BYTES);

    prep_A_kernel<<<(NI * ND + 255) / 256, 256>>>(x);
    prep_B_kernel<<<(NC * 32 + 255) / 256, 256>>>(centers, sigmas);
    dim3 grid(NC / BN, NI / BM);   // (32, 128)
    rbf_mma_kernel<<<grid, 256, SMEM_BYTES>>>(w_lin);
    finalize_kernel<<<NI / 256, 256>>>(b_lin, out);
}

// round 10
// speedup vs baseline: 3.2037x; 1.0019x over previous
#include <cuda_runtime.h>
#include <cuda_fp16.h>
#include <cstdint>

// Problem dims
#define NI 16384
#define NC 4096
#define ND 256
#define KK 512              // fused GEMM K (elements)

// Tiling
#define BM 128
#define BN 128
#define BK 64               // fp16 elems per k-chunk = 128 bytes/row
#define KITERS (KK / BK)    // 8
#define NSTAGE 3
#define CHUNKB 128          // bytes per row per chunk

#define A_TILE_BYTES (BM * CHUNKB)       // 16384
#define B_TILE_BYTES (BN * CHUNKB)       // 16384
#define STAGE_BYTES (A_TILE_BYTES + B_TILE_BYTES)   // 32768
#define SM_A(st) (1024 + (st) * STAGE_BYTES)
#define SM_B(st) (SM_A(st) + A_TILE_BYTES)
#define SMEM_BYTES (1024 + NSTAGE * STAGE_BYTES)    // 99328

// Device scratch, k-chunk-major with SW128 swizzle baked in:
// byte addr = ((kchunk*ROWS + row)*128) + (2*e ^ ((row&7)<<4))
__device__ uint8_t g_A[(size_t)KITERS * NI * CHUNKB];   // 16.8 MB
__device__ uint8_t g_B[(size_t)KITERS * NC * CHUNKB];   //  4.2 MB
__device__ float g_csum[NC];
__device__ float g_score[NI];

// ---------------------------------------------------------------- helpers
__device__ __forceinline__ uint32_t smem_u32(const void* p) {
    uint32_t a;
    asm("{ .reg .u64 t; cvta.to.shared.u64 t, %1; cvt.u32.u64 %0, t; }" : "=r"(a) : "l"(p));
    return a;
}
#define MBAR_INIT(a, n) \
    asm volatile("mbarrier.init.shared.b64 [%0], %1;" :: "r"(a), "r"(n) : "memory")
#define MBAR_EXPECT_TX(a, bytes) \
    asm volatile("mbarrier.arrive.expect_tx.shared.b64 _, [%0], %1;" :: "r"(a), "r"(bytes) : "memory")
#define MBAR_WAIT(a, ph) do {                                                     \
    uint32_t _m = (a), _p = (ph), _d;                                             \
    asm volatile("{ .reg .pred p; mbarrier.try_wait.parity.acquire.cta.shared::cta.b64 p, [%1], %2; selp.b32 %0,1,0,p; }" \
                 : "=r"(_d) : "r"(_m), "r"(_p) : "memory");                       \
    if (!_d) {                                                                    \
        asm volatile("{ .reg .pred P; W%=: mbarrier.try_wait.parity.acquire.cta.shared::cta.b64 P, [%0], %1, 0x989680; @P bra.uni D%=; bra.uni W%=; D%=: }" \
                     :: "r"(_m), "r"(_p) : "memory");                             \
    } } while (0)
#define CP_BULK(dst, src, bytes, mbar) \
    asm volatile("cp.async.bulk.shared::cluster.global.mbarrier::complete_tx::bytes " \
                 "[%0], [%1], %2, [%3];" \
                 :: "r"(dst), "l"(src), "r"(bytes), "r"(mbar) : "memory")

__device__ __forceinline__ void ldm_x4(uint32_t* r, uint32_t addr) {
    asm volatile("ldmatrix.sync.aligned.m8n8.x4.shared.b16 {%0,%1,%2,%3}, [%4];"
                 : "=r"(r[0]), "=r"(r[1]), "=r"(r[2]), "=r"(r[3]) : "r"(addr));
}
// fp16 x fp16 -> fp16 accumulate (half the acc registers; possibly 2x rate)
__device__ __forceinline__ void mma_f16acc(uint32_t* c, const uint32_t* a, const uint32_t* b) {
    asm volatile(
        "mma.sync.aligned.m16n8k16.row.col.f16.f16.f16.f16 "
        "{%0,%1}, {%2,%3,%4,%5}, {%6,%7}, {%0,%1};"
        : "+r"(c[0]), "+r"(c[1])
        : "r"(a[0]), "r"(a[1]), "r"(a[2]), "r"(a[3]), "r"(b[0]), "r"(b[1]));
}

// ---------------------------------------------------------------- prep kernels
__global__ void prep_A_kernel(const float* __restrict__ x) {
    int idx = blockIdx.x * blockDim.x + threadIdx.x;
    if (idx >= NI * ND) return;
    if (idx < NI) g_score[idx] = 0.f;        // fold score zeroing in
    int n = idx >> 8;
    int d = idx & (ND - 1);
    float v = x[idx];
    uint32_t sw = ((uint32_t)(n & 7)) << 4;
    int kch_sq = d >> 6, e = d & 63;
    *(__half*)(g_A + ((size_t)kch_sq * NI + n) * CHUNKB + ((2 * e) ^ sw)) =
        __float2half(v * v);
    *(__half*)(g_A + ((size_t)(4 + kch_sq) * NI + n) * CHUNKB + ((2 * e) ^ sw)) =
        __float2half(v);
}

__global__ void prep_B_kernel(const float* __restrict__ centers,
                              const float* __restrict__ sigmas) {
    int warp = (blockIdx.x * blockDim.x + threadIdx.x) >> 5;
    int lane = threadIdx.x & 31;
    if (warp >= NC) return;
    int c = warp;
    uint32_t sw = ((uint32_t)(c & 7)) << 4;
    float acc = 0.f;
    #pragma unroll
    for (int d = lane; d < ND; d += 32) {
        float s   = sigmas[c * ND + d];
        float ce  = centers[c * ND + d];
        float inv = 1.0f / (2.0f * s * s);
        int kch = d >> 6, e = d & 63;
        *(__half*)(g_B + ((size_t)kch * NC + c) * CHUNKB + ((2 * e) ^ sw)) =
            __float2half(inv);
        *(__half*)(g_B + ((size_t)(4 + kch) * NC + c) * CHUNKB + ((2 * e) ^ sw)) =
            __float2half(-2.0f * ce * inv);
        acc = fmaf(ce * ce, inv, acc);
    }
    #pragma unroll
    for (int m = 16; m; m >>= 1) acc += __shfl_xor_sync(0xffffffffu, acc, m);
    if (lane == 0) g_csum[c] = acc;
}

// ---------------------------------------------------------------- main kernel
__global__ void __launch_bounds__(256, 2)
rbf_mma_kernel(const float* __restrict__ w_lin) {
    extern __shared__ char smem[];
    const uint32_t smem_base = smem_u32(smem);
    const int tid  = threadIdx.x;
    const int lane = tid & 31;
    const int wid  = tid >> 5;
    const int wm   = wid >> 2;      // 0..1  (M)
    const int wn   = wid & 3;       // 0..3  (N)
    const int bn   = blockIdx.x;    // center tile
    const int bm   = blockIdx.y;    // input tile

    if (tid == 0) {
        MBAR_INIT(smem_base + 0, 1);
        MBAR_INIT(smem_base + 8, 1);
        MBAR_INIT(smem_base + 16, 1);
    }
    __syncthreads();

    auto issue_stage = [&](int st, int kiter) {
        uint32_t mb = smem_base + st * 8;
        MBAR_EXPECT_TX(mb, STAGE_BYTES);
        const uint8_t* srcA = g_A + ((size_t)kiter * NI + bm * BM) * CHUNKB;
        const uint8_t* srcB = g_B + ((size_t)kiter * NC + bn * BN) * CHUNKB;
        CP_BULK(smem_base + SM_A(st), (const void*)srcA, A_TILE_BYTES, mb);
        CP_BULK(smem_base + SM_B(st), (const void*)srcB, B_TILE_BYTES, mb);
    };

    if (tid == 0) {
        issue_stage(0, 0);
        issue_stage(1, 1);
        issue_stage(2, 2);
    }

    // fp16 accumulators: 2 regs per m16n8 tile
    uint32_t acc[4][4][2];
    #pragma unroll
    for (int mt = 0; mt < 4; mt++)
        #pragma unroll
        for (int nt = 0; nt < 4; nt++) { acc[mt][nt][0] = 0u; acc[mt][nt][1] = 0u; }

    #pragma unroll 1
    for (int k = 0; k < KITERS; k++) {
        const int st = k % NSTAGE;
        MBAR_WAIT(smem_base + st * 8, (k / NSTAGE) & 1);

        const uint32_t aBase = smem_base + SM_A(st);
        const uint32_t bBase = smem_base + SM_B(st);

        // Preload ALL B fragments for this stage (8 merged ldm_x4 -> 32 regs)
        uint32_t b[4][4][2];     // [kc][nt][2]
        #pragma unroll
        for (int kc = 0; kc < 4; kc++) {
            #pragma unroll
            for (int p = 0; p < 2; p++) {
                int g = lane >> 3;            // 0..3: {t0 k0, t0 k8, t1 k0, t1 k8}
                int trow = wn * 32 + p * 16 + (g >> 1) * 8 + (lane & 7);
                uint32_t boff = kc * 32 + ((g & 1) << 4);
                uint32_t addr = bBase + trow * CHUNKB + (boff ^ ((trow & 7) << 4));
                uint32_t bp[4];
                ldm_x4(bp, addr);
                b[kc][2 * p][0] = bp[0]; b[kc][2 * p][1] = bp[1];
                b[kc][2 * p + 1][0] = bp[2]; b[kc][2 * p + 1][1] = bp[3];
            }
        }

        #pragma unroll
        for (int kc = 0; kc < 4; kc++) {           // 4 x k16 per stage
            uint32_t a[4][4];
            #pragma unroll
            for (int mt = 0; mt < 4; mt++) {
                int row = wm * 64 + mt * 16 + (lane & 15);
                uint32_t boff = kc * 32 + ((lane >> 4) << 4);
                uint32_t addr = aBase + row * CHUNKB + (boff ^ ((row & 7) << 4));
                ldm_x4(a[mt], addr);
            }
            #pragma unroll
            for (int mt = 0; mt < 4; mt++)
                #pragma unroll
                for (int nt = 0; nt < 4; nt++)
                    mma_f16acc(acc[mt][nt], a[mt], b[kc][nt]);
        }

        // all warps done reading stage st -> safe to refill it with k+3
        __syncthreads();
        if (tid == 0 && k + NSTAGE < KITERS) issue_stage(st, k + NSTAGE);
    }

    // ---------------- epilogue: d2 = acc + csum; add exp(-d2)*w only if d2<60
    const int cBase = bn * BN + wn * 32;
    float cs[4][2], wv[4][2];
    #pragma unroll
    for (int nt = 0; nt < 4; nt++)
        #pragma unroll
        for (int j = 0; j < 2; j++) {
            int c = cBase + nt * 8 + (lane & 3) * 2 + j;
            cs[nt][j] = __ldg(&g_csum[c]);
            wv[nt][j] = __ldg(&w_lin[c]);
        }

    float mn = 1e30f;
    #pragma unroll
    for (int mt = 0; mt < 4; mt++)
        #pragma unroll
        for (int nt = 0; nt < 4; nt++)
            #pragma unroll
            for (int h = 0; h < 2; h++) {
                __half2 hv = *reinterpret_cast<__half2*>(&acc[mt][nt][h]);
                mn = fminf(mn, __low2float(hv)  + cs[nt][0]);
                mn = fminf(mn, __high2float(hv) + cs[nt][1]);
            }

    if (__any_sync(0xffffffffu, mn < 60.f)) {       // rare path
        float rs[4][2];
        #pragma unroll
        for (int mt = 0; mt < 4; mt++) { rs[mt][0] = 0.f; rs[mt][1] = 0.f; }
        #pragma unroll
        for (int mt = 0; mt < 4; mt++)
            #pragma unroll
            for (int nt = 0; nt < 4; nt++)
                #pragma unroll
                for (int h = 0; h < 2; h++) {
                    __half2 hv = *reinterpret_cast<__half2*>(&acc[mt][nt][h]);
                    float d2a = __low2float(hv)  + cs[nt][0];
                    float d2b = __high2float(hv) + cs[nt][1];
                    if (d2a < 60.f)
                        rs[mt][h] = fmaf(__expf(-d2a), wv[nt][0], rs[mt][h]);
                    if (d2b < 60.f)
                        rs[mt][h] = fmaf(__expf(-d2b), wv[nt][1], rs[mt][h]);
                }
        #pragma unroll
        for (int mt = 0; mt < 4; mt++)
            #pragma unroll
            for (int h = 0; h < 2; h++) {
                float v = rs[mt][h];
                v += __shfl_xor_sync(0xffffffffu, v, 1);
                v += __shfl_xor_sync(0xffffffffu, v, 2);
                if ((lane & 3) == 0)
                    atomicAdd(&g_score[bm * BM + wm * 64 + mt * 16 + h * 8 + (lane >> 2)], v);
            }
    }
    // fast path: contributions are 0; g_score pre-zeroed -> nothing to do
}

__global__ void finalize_kernel(const float* __restrict__ b_lin,
                                float* __restrict__ out) {
    int n = blockIdx.x * blockDim.x + threadIdx.x;
    if (n < NI) {
        float s = g_score[n] + b_lin[0];
        out[n] = 1.0f / (1.0f + __expf(-s));
    }
}

// ---------------------------------------------------------------- launch
extern "C" void kernel_launch(void* const* d_in, const int* in_sizes, int n_in,
                              void* d_out, int out_size) {
    const float* x       = (const float*)d_in[0];
    const float* centers = (const float*)d_in[1];
    const float* sigmas  = (const float*)d_in[2];
    const float* w_lin   = (const float*)d_in[3];
    const float* b_lin   = (const float*)d_in[4];
    float* out = (float*)d_out;

    cudaFuncSetAttribute(rbf_mma_kernel,
                         cudaFuncAttributeMaxDynamicSharedMemorySize, SMEM_BYTES);

    prep_A_kernel<<<(NI * ND + 255) / 256, 256>>>(x);
    prep_B_kernel<<<(NC * 32 + 255) / 256, 256>>>(centers, sigmas);
    dim3 grid(NC / BN, NI / BM);   // (32, 128)
    rbf_mma_kernel<<<grid, 256, SMEM_BYTES>>>(w_lin);
    finalize_kernel<<<NI / 256, 256>>>(b_lin, out);
}

// round 11
// speedup vs baseline: 3.4767x; 1.0852x over previous
#include <cuda_runtime.h>
#include <cuda_fp16.h>
#include <cstdint>

// Problem dims
#define NI 16384
#define NC 4096
#define ND 256
#define KK 512              // fused GEMM K (elements)

// Tiling
#define BM 128
#define BN 128
#define BK 64               // fp16 elems per k-chunk = 128 bytes/row
#define KITERS (KK / BK)    // 8
#define NSTAGE 2
#define CHUNKB 128          // bytes per row per chunk

#define A_TILE_BYTES (BM * CHUNKB)       // 16384
#define B_TILE_BYTES (BN * CHUNKB)       // 16384
#define STAGE_BYTES (A_TILE_BYTES + B_TILE_BYTES)   // 32768
#define SM_A(st) (1024 + (st) * STAGE_BYTES)
#define SM_B(st) (SM_A(st) + A_TILE_BYTES)
#define SMEM_BYTES (1024 + NSTAGE * STAGE_BYTES)    // 66560 -> 3 CTAs/SM

// Device scratch, k-chunk-major with SW128 swizzle baked in:
// byte addr = ((kchunk*ROWS + row)*128) + (2*e ^ ((row&7)<<4))
__device__ uint8_t g_A[(size_t)KITERS * NI * CHUNKB];   // 16.8 MB
__device__ uint8_t g_B[(size_t)KITERS * NC * CHUNKB];   //  4.2 MB
__device__ float g_csum[NC];
__device__ float g_score[NI];

// ---------------------------------------------------------------- helpers
__device__ __forceinline__ uint32_t smem_u32(const void* p) {
    uint32_t a;
    asm("{ .reg .u64 t; cvta.to.shared.u64 t, %1; cvt.u32.u64 %0, t; }" : "=r"(a) : "l"(p));
    return a;
}
#define MBAR_INIT(a, n) \
    asm volatile("mbarrier.init.shared.b64 [%0], %1;" :: "r"(a), "r"(n) : "memory")
#define MBAR_EXPECT_TX(a, bytes) \
    asm volatile("mbarrier.arrive.expect_tx.shared.b64 _, [%0], %1;" :: "r"(a), "r"(bytes) : "memory")
#define MBAR_WAIT(a, ph) do {                                                     \
    uint32_t _m = (a), _p = (ph), _d;                                             \
    asm volatile("{ .reg .pred p; mbarrier.try_wait.parity.acquire.cta.shared::cta.b64 p, [%1], %2; selp.b32 %0,1,0,p; }" \
                 : "=r"(_d) : "r"(_m), "r"(_p) : "memory");                       \
    if (!_d) {                                                                    \
        asm volatile("{ .reg .pred P; W%=: mbarrier.try_wait.parity.acquire.cta.shared::cta.b64 P, [%0], %1, 0x989680; @P bra.uni D%=; bra.uni W%=; D%=: }" \
                     :: "r"(_m), "r"(_p) : "memory");                             \
    } } while (0)
#define CP_BULK(dst, src, bytes, mbar) \
    asm volatile("cp.async.bulk.shared::cluster.global.mbarrier::complete_tx::bytes " \
                 "[%0], [%1], %2, [%3];" \
                 :: "r"(dst), "l"(src), "r"(bytes), "r"(mbar) : "memory")

__device__ __forceinline__ void ldm_x4(uint32_t* r, uint32_t addr) {
    asm volatile("ldmatrix.sync.aligned.m8n8.x4.shared.b16 {%0,%1,%2,%3}, [%4];"
                 : "=r"(r[0]), "=r"(r[1]), "=r"(r[2]), "=r"(r[3]) : "r"(addr));
}
// fp16 x fp16 -> fp16 accumulate (32 acc regs total)
__device__ __forceinline__ void mma_f16acc(uint32_t* c, const uint32_t* a, const uint32_t* b) {
    asm volatile(
        "mma.sync.aligned.m16n8k16.row.col.f16.f16.f16.f16 "
        "{%0,%1}, {%2,%3,%4,%5}, {%6,%7}, {%0,%1};"
        : "+r"(c[0]), "+r"(c[1])
        : "r"(a[0]), "r"(a[1]), "r"(a[2]), "r"(a[3]), "r"(b[0]), "r"(b[1]));
}

// ---------------------------------------------------------------- prep kernels
__global__ void prep_A_kernel(const float* __restrict__ x) {
    int idx = blockIdx.x * blockDim.x + threadIdx.x;
    if (idx >= NI * ND) return;
    if (idx < NI) g_score[idx] = 0.f;        // fold score zeroing in
    int n = idx >> 8;
    int d = idx & (ND - 1);
    float v = x[idx];
    uint32_t sw = ((uint32_t)(n & 7)) << 4;
    int kch_sq = d >> 6, e = d & 63;
    *(__half*)(g_A + ((size_t)kch_sq * NI + n) * CHUNKB + ((2 * e) ^ sw)) =
        __float2half(v * v);
    *(__half*)(g_A + ((size_t)(4 + kch_sq) * NI + n) * CHUNKB + ((2 * e) ^ sw)) =
        __float2half(v);
}

__global__ void prep_B_kernel(const float* __restrict__ centers,
                              const float* __restrict__ sigmas) {
    int warp = (blockIdx.x * blockDim.x + threadIdx.x) >> 5;
    int lane = threadIdx.x & 31;
    if (warp >= NC) return;
    int c = warp;
    uint32_t sw = ((uint32_t)(c & 7)) << 4;
    float acc = 0.f;
    #pragma unroll
    for (int d = lane; d < ND; d += 32) {
        float s   = sigmas[c * ND + d];
        float ce  = centers[c * ND + d];
        float inv = 1.0f / (2.0f * s * s);
        int kch = d >> 6, e = d & 63;
        *(__half*)(g_B + ((size_t)kch * NC + c) * CHUNKB + ((2 * e) ^ sw)) =
            __float2half(inv);
        *(__half*)(g_B + ((size_t)(4 + kch) * NC + c) * CHUNKB + ((2 * e) ^ sw)) =
            __float2half(-2.0f * ce * inv);
        acc = fmaf(ce * ce, inv, acc);
    }
    #pragma unroll
    for (int m = 16; m; m >>= 1) acc += __shfl_xor_sync(0xffffffffu, acc, m);
    if (lane == 0) g_csum[c] = acc;
}

// ---------------------------------------------------------------- main kernel
__global__ void __launch_bounds__(256, 3)
rbf_mma_kernel(const float* __restrict__ w_lin) {
    extern __shared__ char smem[];
    const uint32_t smem_base = smem_u32(smem);
    const int tid  = threadIdx.x;
    const int lane = tid & 31;
    const int wid  = tid >> 5;
    const int wm   = wid >> 2;      // 0..1  (M)
    const int wn   = wid & 3;       // 0..3  (N)
    const int bn   = blockIdx.x;    // center tile
    const int bm   = blockIdx.y;    // input tile

    if (tid == 0) {
        MBAR_INIT(smem_base + 0, 1);
        MBAR_INIT(smem_base + 8, 1);
    }
    __syncthreads();

    auto issue_stage = [&](int st, int kiter) {
        uint32_t mb = smem_base + st * 8;
        MBAR_EXPECT_TX(mb, STAGE_BYTES);
        const uint8_t* srcA = g_A + ((size_t)kiter * NI + bm * BM) * CHUNKB;
        const uint8_t* srcB = g_B + ((size_t)kiter * NC + bn * BN) * CHUNKB;
        CP_BULK(smem_base + SM_A(st), (const void*)srcA, A_TILE_BYTES, mb);
        CP_BULK(smem_base + SM_B(st), (const void*)srcB, B_TILE_BYTES, mb);
    };

    if (tid == 0) {
        issue_stage(0, 0);
        issue_stage(1, 1);
    }

    // fp16 accumulators: 2 regs per m16n8 tile -> 32 regs
    uint32_t acc[4][4][2];
    #pragma unroll
    for (int mt = 0; mt < 4; mt++)
        #pragma unroll
        for (int nt = 0; nt < 4; nt++) { acc[mt][nt][0] = 0u; acc[mt][nt][1] = 0u; }

    #pragma unroll 1
    for (int k = 0; k < KITERS; k++) {
        const int st = k & 1;
        MBAR_WAIT(smem_base + st * 8, (k >> 1) & 1);

        const uint32_t aBase = smem_base + SM_A(st);
        const uint32_t bBase = smem_base + SM_B(st);
        #pragma unroll
        for (int kc = 0; kc < 4; kc++) {           // 4 x k16 per stage
            uint32_t a[4][4], b[4][2];
            #pragma unroll
            for (int mt = 0; mt < 4; mt++) {
                int row = wm * 64 + mt * 16 + (lane & 15);
                uint32_t boff = kc * 32 + ((lane >> 4) << 4);
                uint32_t addr = aBase + row * CHUNKB + (boff ^ ((row & 7) << 4));
                ldm_x4(a[mt], addr);
            }
            // B: 2 merged x4 loads; each covers two n8-tiles (k0+k8 fragments)
            #pragma unroll
            for (int p = 0; p < 2; p++) {
                int g = lane >> 3;            // 0..3: {t0 k0, t0 k8, t1 k0, t1 k8}
                int trow = wn * 32 + p * 16 + (g >> 1) * 8 + (lane & 7);
                uint32_t boff = kc * 32 + ((g & 1) << 4);
                uint32_t addr = bBase + trow * CHUNKB + (boff ^ ((trow & 7) << 4));
                uint32_t bp[4];
                ldm_x4(bp, addr);
                b[2 * p][0] = bp[0]; b[2 * p][1] = bp[1];
                b[2 * p + 1][0] = bp[2]; b[2 * p + 1][1] = bp[3];
            }
            #pragma unroll
            for (int mt = 0; mt < 4; mt++)
                #pragma unroll
                for (int nt = 0; nt < 4; nt++)
                    mma_f16acc(acc[mt][nt], a[mt], b[nt]);
        }

        // all warps done reading stage st -> safe to refill it with k+2
        __syncthreads();
        if (tid == 0 && k + NSTAGE < KITERS) issue_stage(st, k + NSTAGE);
    }

    // ---------------- epilogue: d2 = acc + csum; add exp(-d2)*w only if d2<60
    const int cBase = bn * BN + wn * 32;
    float cs[4][2], wv[4][2];
    #pragma unroll
    for (int nt = 0; nt < 4; nt++)
        #pragma unroll
        for (int j = 0; j < 2; j++) {
            int c = cBase + nt * 8 + (lane & 3) * 2 + j;
            cs[nt][j] = __ldg(&g_csum[c]);
            wv[nt][j] = __ldg(&w_lin[c]);
        }

    float mn = 1e30f;
    #pragma unroll
    for (int mt = 0; mt < 4; mt++)
        #pragma unroll
        for (int nt = 0; nt < 4; nt++)
            #pragma unroll
            for (int h = 0; h < 2; h++) {
                __half2 hv = *reinterpret_cast<__half2*>(&acc[mt][nt][h]);
                mn = fminf(mn, __low2float(hv)  + cs[nt][0]);
                mn = fminf(mn, __high2float(hv) + cs[nt][1]);
            }

    if (__any_sync(0xffffffffu, mn < 60.f)) {       // rare path
        float rs[4][2];
        #pragma unroll
        for (int mt = 0; mt < 4; mt++) { rs[mt][0] = 0.f; rs[mt][1] = 0.f; }
        #pragma unroll
        for (int mt = 0; mt < 4; mt++)
            #pragma unroll
            for (int nt = 0; nt < 4; nt++)
                #pragma unroll
                for (int h = 0; h < 2; h++) {
                    __half2 hv = *reinterpret_cast<__half2*>(&acc[mt][nt][h]);
                    float d2a = __low2float(hv)  + cs[nt][0];
                    float d2b = __high2float(hv) + cs[nt][1];
                    if (d2a < 60.f)
                        rs[mt][h] = fmaf(__expf(-d2a), wv[nt][0], rs[mt][h]);
                    if (d2b < 60.f)
                        rs[mt][h] = fmaf(__expf(-d2b), wv[nt][1], rs[mt][h]);
                }
        #pragma unroll
        for (int mt = 0; mt < 4; mt++)
            #pragma unroll
            for (int h = 0; h < 2; h++) {
                float v = rs[mt][h];
                v += __shfl_xor_sync(0xffffffffu, v, 1);
                v += __shfl_xor_sync(0xffffffffu, v, 2);
                if ((lane & 3) == 0)
                    atomicAdd(&g_score[bm * BM + wm * 64 + mt * 16 + h * 8 + (lane >> 2)], v);
            }
    }
    // fast path: contributions are 0; g_score pre-zeroed -> nothing to do
}

__global__ void finalize_kernel(const float* __restrict__ b_lin,
                                float* __restrict__ out) {
    int n = blockIdx.x * blockDim.x + threadIdx.x;
    if (n < NI) {
        float s = g_score[n] + b_lin[0];
        out[n] = 1.0f / (1.0f + __expf(-s));
    }
}

// ---------------------------------------------------------------- launch
extern "C" void kernel_launch(void* const* d_in, const int* in_sizes, int n_in,
                              void* d_out, int out_size) {
    const float* x       = (const float*)d_in[0];
    const float* centers = (const float*)d_in[1];
    const float* sigmas  = (const float*)d_in[2];
    const float* w_lin   = (const float*)d_in[3];
    const float* b_lin   = (const float*)d_in[4];
    float* out = (float*)d_out;

    cudaFuncSetAttribute(rbf_mma_kernel,
                         cudaFuncAttributeMaxDynamicSharedMemorySize, SMEM_BYTES);

    prep_A_kernel<<<(NI * ND + 255) / 256, 256>>>(x);
    prep_B_kernel<<<(NC * 32 + 255) / 256, 256>>>(centers, sigmas);
    dim3 grid(NC / BN, NI / BM);   // (32, 128)
    rbf_mma_kernel<<<grid, 256, SMEM_BYTES>>>(w_lin);
    finalize_kernel<<<NI / 256, 256>>>(b_lin, out);
}

// round 12
// speedup vs baseline: 4.1437x; 1.1919x over previous
#include <cuda_runtime.h>
#include <cuda_fp16.h>
#include <cstdint>

// Problem dims
#define NI 16384
#define NC 4096
#define ND 256
#define KD 192              // screened dims
#define KK 384              // fused screen-GEMM K = 2*KD

// Screen: skip pair when fp16 partial d2 (lower bound of full d2, slack 1.0)
// >= TSCREEN. Partial ~ N(64, 8.4^2) -> z=5.0 -> per-pair P~3e-7.
// Skipped mass <= NC * e^-(T-1) * max|w| ~ 2e-7 << tolerance.
#define TSCREEN 22.0f

// Tiling
#define BM 128
#define BN 128
#define BK 64               // fp16 elems per k-chunk = 128 bytes/row
#define KITERS (KK / BK)    // 6
#define NSTAGE 2
#define CHUNKB 128          // bytes per row per chunk

#define A_TILE_BYTES (BM * CHUNKB)       // 16384
#define B_TILE_BYTES (BN * CHUNKB)       // 16384
#define STAGE_BYTES (A_TILE_BYTES + B_TILE_BYTES)   // 32768
#define SM_A(st) (1024 + (st) * STAGE_BYTES)
#define SM_B(st) (SM_A(st) + A_TILE_BYTES)
#define SMEM_BYTES (1024 + NSTAGE * STAGE_BYTES)    // 66560 -> 3 CTAs/SM

// Device scratch, k-chunk-major with SW128 swizzle baked in
__device__ uint8_t g_A[(size_t)KITERS * NI * CHUNKB];   // 12.6 MB
__device__ uint8_t g_B[(size_t)KITERS * NC * CHUNKB];   //  3.1 MB
__device__ float g_csum[NC];                            // sum over d<192
__device__ float g_score[NI];

// ---------------------------------------------------------------- helpers
__device__ __forceinline__ uint32_t smem_u32(const void* p) {
    uint32_t a;
    asm("{ .reg .u64 t; cvta.to.shared.u64 t, %1; cvt.u32.u64 %0, t; }" : "=r"(a) : "l"(p));
    return a;
}
#define MBAR_INIT(a, n) \
    asm volatile("mbarrier.init.shared.b64 [%0], %1;" :: "r"(a), "r"(n) : "memory")
#define MBAR_EXPECT_TX(a, bytes) \
    asm volatile("mbarrier.arrive.expect_tx.shared.b64 _, [%0], %1;" :: "r"(a), "r"(bytes) : "memory")
#define MBAR_WAIT(a, ph) do {                                                     \
    uint32_t _m = (a), _p = (ph), _d;                                             \
    asm volatile("{ .reg .pred p; mbarrier.try_wait.parity.acquire.cta.shared::cta.b64 p, [%1], %2; selp.b32 %0,1,0,p; }" \
                 : "=r"(_d) : "r"(_m), "r"(_p) : "memory");                       \
    if (!_d) {                                                                    \
        asm volatile("{ .reg .pred P; W%=: mbarrier.try_wait.parity.acquire.cta.shared::cta.b64 P, [%0], %1, 0x989680; @P bra.uni D%=; bra.uni W%=; D%=: }" \
                     :: "r"(_m), "r"(_p) : "memory");                             \
    } } while (0)
#define CP_BULK(dst, src, bytes, mbar) \
    asm volatile("cp.async.bulk.shared::cluster.global.mbarrier::complete_tx::bytes " \
                 "[%0], [%1], %2, [%3];" \
                 :: "r"(dst), "l"(src), "r"(bytes), "r"(mbar) : "memory")

__device__ __forceinline__ void ldm_x4(uint32_t* r, uint32_t addr) {
    asm volatile("ldmatrix.sync.aligned.m8n8.x4.shared.b16 {%0,%1,%2,%3}, [%4];"
                 : "=r"(r[0]), "=r"(r[1]), "=r"(r[2]), "=r"(r[3]) : "r"(addr));
}
__device__ __forceinline__ void mma_f16acc(uint32_t* c, const uint32_t* a, const uint32_t* b) {
    asm volatile(
        "mma.sync.aligned.m16n8k16.row.col.f16.f16.f16.f16 "
        "{%0,%1}, {%2,%3,%4,%5}, {%6,%7}, {%0,%1};"
        : "+r"(c[0]), "+r"(c[1])
        : "r"(a[0]), "r"(a[1]), "r"(a[2]), "r"(a[3]), "r"(b[0]), "r"(b[1]));
}

// ---------------------------------------------------------------- prep kernels
__global__ void prep_A_kernel(const float* __restrict__ x) {
    int idx = blockIdx.x * blockDim.x + threadIdx.x;
    if (idx >= NI * KD) return;
    if (idx < NI) g_score[idx] = 0.f;        // fold score zeroing in
    int n = idx / KD;
    int d = idx % KD;
    float v = x[n * ND + d];
    uint32_t sw = ((uint32_t)(n & 7)) << 4;
    int kch = d >> 6, e = d & 63;            // kch 0..2
    *(__half*)(g_A + ((size_t)kch * NI + n) * CHUNKB + ((2 * e) ^ sw)) =
        __float2half(v * v);
    *(__half*)(g_A + ((size_t)(3 + kch) * NI + n) * CHUNKB + ((2 * e) ^ sw)) =
        __float2half(v);
}

__global__ void prep_B_kernel(const float* __restrict__ centers,
                              const float* __restrict__ sigmas) {
    int warp = (blockIdx.x * blockDim.x + threadIdx.x) >> 5;
    int lane = threadIdx.x & 31;
    if (warp >= NC) return;
    int c = warp;
    uint32_t sw = ((uint32_t)(c & 7)) << 4;
    float acc = 0.f;
    #pragma unroll
    for (int d = lane; d < KD; d += 32) {
        float s   = sigmas[c * ND + d];
        float ce  = centers[c * ND + d];
        float inv = 1.0f / (2.0f * s * s);
        int kch = d >> 6, e = d & 63;
        *(__half*)(g_B + ((size_t)kch * NC + c) * CHUNKB + ((2 * e) ^ sw)) =
            __float2half(inv);
        *(__half*)(g_B + ((size_t)(3 + kch) * NC + c) * CHUNKB + ((2 * e) ^ sw)) =
            __float2half(-2.0f * ce * inv);
        acc = fmaf(ce * ce, inv, acc);
    }
    #pragma unroll
    for (int m = 16; m; m >>= 1) acc += __shfl_xor_sync(0xffffffffu, acc, m);
    if (lane == 0) g_csum[c] = acc;
}

// ---------------------------------------------------------------- main kernel
__global__ void __launch_bounds__(256, 3)
rbf_mma_kernel(const float* __restrict__ x,
               const float* __restrict__ centers,
               const float* __restrict__ sigmas,
               const float* __restrict__ w_lin) {
    extern __shared__ char smem[];
    const uint32_t smem_base = smem_u32(smem);
    const int tid  = threadIdx.x;
    const int lane = tid & 31;
    const int wid  = tid >> 5;
    const int wm   = wid >> 2;      // 0..1  (M)
    const int wn   = wid & 3;       // 0..3  (N)
    const int bn   = blockIdx.x;    // center tile
    const int bm   = blockIdx.y;    // input tile

    if (tid == 0) {
        MBAR_INIT(smem_base + 0, 1);
        MBAR_INIT(smem_base + 8, 1);
    }
    __syncthreads();

    auto issue_stage = [&](int st, int kiter) {
        uint32_t mb = smem_base + st * 8;
        MBAR_EXPECT_TX(mb, STAGE_BYTES);
        const uint8_t* srcA = g_A + ((size_t)kiter * NI + bm * BM) * CHUNKB;
        const uint8_t* srcB = g_B + ((size_t)kiter * NC + bn * BN) * CHUNKB;
        CP_BULK(smem_base + SM_A(st), (const void*)srcA, A_TILE_BYTES, mb);
        CP_BULK(smem_base + SM_B(st), (const void*)srcB, B_TILE_BYTES, mb);
    };

    if (tid == 0) {
        issue_stage(0, 0);
        issue_stage(1, 1);
    }

    // fp16 accumulators: 2 regs per m16n8 tile -> 32 regs
    uint32_t acc[4][4][2];
    #pragma unroll
    for (int mt = 0; mt < 4; mt++)
        #pragma unroll
        for (int nt = 0; nt < 4; nt++) { acc[mt][nt][0] = 0u; acc[mt][nt][1] = 0u; }

    #pragma unroll 1
    for (int k = 0; k < KITERS; k++) {
        const int st = k & 1;
        MBAR_WAIT(smem_base + st * 8, (k >> 1) & 1);

        const uint32_t aBase = smem_base + SM_A(st);
        const uint32_t bBase = smem_base + SM_B(st);
        #pragma unroll
        for (int kc = 0; kc < 4; kc++) {           // 4 x k16 per stage
            uint32_t a[4][4], b[4][2];
            #pragma unroll
            for (int mt = 0; mt < 4; mt++) {
                int row = wm * 64 + mt * 16 + (lane & 15);
                uint32_t boff = kc * 32 + ((lane >> 4) << 4);
                uint32_t addr = aBase + row * CHUNKB + (boff ^ ((row & 7) << 4));
                ldm_x4(a[mt], addr);
            }
            #pragma unroll
            for (int p = 0; p < 2; p++) {
                int g = lane >> 3;            // 0..3: {t0 k0, t0 k8, t1 k0, t1 k8}
                int trow = wn * 32 + p * 16 + (g >> 1) * 8 + (lane & 7);
                uint32_t boff = kc * 32 + ((g & 1) << 4);
                uint32_t addr = bBase + trow * CHUNKB + (boff ^ ((trow & 7) << 4));
                uint32_t bp[4];
                ldm_x4(bp, addr);
                b[2 * p][0] = bp[0]; b[2 * p][1] = bp[1];
                b[2 * p + 1][0] = bp[2]; b[2 * p + 1][1] = bp[3];
            }
            #pragma unroll
            for (int mt = 0; mt < 4; mt++)
                #pragma unroll
                for (int nt = 0; nt < 4; nt++)
                    mma_f16acc(acc[mt][nt], a[mt], b[nt]);
        }

        __syncthreads();
        if (tid == 0 && k + NSTAGE < KITERS) issue_stage(st, k + NSTAGE);
    }

    // ---------------- epilogue: p = partial d2 over 192 dims (lower bound).
    // Skip if p >= TSCREEN; else compute remaining 64 dims exactly (fp32).
    const int cBase = bn * BN + wn * 32;
    float cs[4][2];
    #pragma unroll
    for (int nt = 0; nt < 4; nt++)
        #pragma unroll
        for (int j = 0; j < 2; j++)
            cs[nt][j] = __ldg(&g_csum[cBase + nt * 8 + (lane & 3) * 2 + j]);

    float mn = 1e30f;
    #pragma unroll
    for (int mt = 0; mt < 4; mt++)
        #pragma unroll
        for (int nt = 0; nt < 4; nt++)
            #pragma unroll
            for (int h = 0; h < 2; h++) {
                __half2 hv = *reinterpret_cast<__half2*>(&acc[mt][nt][h]);
                mn = fminf(mn, __low2float(hv)  + cs[nt][0]);
                mn = fminf(mn, __high2float(hv) + cs[nt][1]);
            }

    if (__any_sync(0xffffffffu, mn < TSCREEN)) {    // very rare (z~5 tail)
        float rs[4][2];
        #pragma unroll
        for (int mt = 0; mt < 4; mt++) { rs[mt][0] = 0.f; rs[mt][1] = 0.f; }
        #pragma unroll 1
        for (int mt = 0; mt < 4; mt++)
            #pragma unroll 1
            for (int nt = 0; nt < 4; nt++)
                #pragma unroll 1
                for (int h = 0; h < 2; h++) {
                    __half2 hv = *reinterpret_cast<__half2*>(&acc[mt][nt][h]);
                    float pv[2] = { __low2float(hv)  + cs[nt][0],
                                    __high2float(hv) + cs[nt][1] };
                    #pragma unroll 1
                    for (int j = 0; j < 2; j++) {
                        if (pv[j] < TSCREEN) {
                            int row = bm * BM + wm * 64 + mt * 16 + h * 8 + (lane >> 2);
                            int col = cBase + nt * 8 + (lane & 3) * 2 + j;
                            float rest = 0.f;
                            for (int d = KD; d < ND; d++) {
                                float xv = x[row * ND + d];
                                float cv = centers[col * ND + d];
                                float sv = sigmas[col * ND + d];
                                float df = xv - cv;
                                rest += (df * df) / (2.0f * sv * sv);
                            }
                            float d2 = pv[j] + rest;
                            if (d2 < 60.f)
                                rs[mt][h] = fmaf(expf(-d2), __ldg(&w_lin[col]), rs[mt][h]);
                        }
                    }
                }
        #pragma unroll
        for (int mt = 0; mt < 4; mt++)
            #pragma unroll
            for (int h = 0; h < 2; h++) {
                float v = rs[mt][h];
                v += __shfl_xor_sync(0xffffffffu, v, 1);
                v += __shfl_xor_sync(0xffffffffu, v, 2);
                if ((lane & 3) == 0)
                    atomicAdd(&g_score[bm * BM + wm * 64 + mt * 16 + h * 8 + (lane >> 2)], v);
            }
    }
    // fast path: skipped mass ~2e-7; g_score pre-zeroed
}

__global__ void finalize_kernel(const float* __restrict__ b_lin,
                                float* __restrict__ out) {
    int n = blockIdx.x * blockDim.x + threadIdx.x;
    if (n < NI) {
        float s = g_score[n] + b_lin[0];
        out[n] = 1.0f / (1.0f + __expf(-s));
    }
}

// ---------------------------------------------------------------- launch
extern "C" void kernel_launch(void* const* d_in, const int* in_sizes, int n_in,
                              void* d_out, int out_size) {
    const float* x       = (const float*)d_in[0];
    const float* centers = (const float*)d_in[1];
    const float* sigmas  = (const float*)d_in[2];
    const float* w_lin   = (const float*)d_in[3];
    const float* b_lin   = (const float*)d_in[4];
    float* out = (float*)d_out;

    cudaFuncSetAttribute(rbf_mma_kernel,
                         cudaFuncAttributeMaxDynamicSharedMemorySize, SMEM_BYTES);

    prep_A_kernel<<<(NI * KD + 255) / 256, 256>>>(x);
    prep_B_kernel<<<(NC * 32 + 255) / 256, 256>>>(centers, sigmas);
    dim3 grid(NC / BN, NI / BM);   // (32, 128)
    rbf_mma_kernel<<<grid, 256, SMEM_BYTES>>>(x, centers, sigmas, w_lin);
    finalize_kernel<<<NI / 256, 256>>>(b_lin, out);
}

// round 13
// speedup vs baseline: 5.7077x; 1.3774x over previous
#include <cuda_runtime.h>
#include <cuda_fp16.h>
#include <cstdint>

// Problem dims
#define NI 16384
#define NC 4096
#define ND 256
#define KD 128              // screened dims
#define KK 256              // fused screen-GEMM K = 2*KD

// Screen: skip pair when fp16 partial d2 (lower bound of full d2, slack 1.0)
// >= TSCREEN. Partial ~ N(42.7, 6.9^2) -> z=4.16 -> per-pair P<=1.6e-5,
// per-warp trigger ~3%. Skipped mass <= NC*e^-(T-1)*|w| ~ 4.6e-4 on score
// -> ~2.3e-4 rel on output, and that's the degenerate worst case.
#define TSCREEN 14.0f

// Tiling
#define BM 128
#define BN 128
#define BK 64               // fp16 elems per k-chunk = 128 bytes/row
#define KITERS (KK / BK)    // 4
#define NSTAGE 2
#define CHUNKB 128          // bytes per row per chunk

#define A_TILE_BYTES (BM * CHUNKB)       // 16384
#define B_TILE_BYTES (BN * CHUNKB)       // 16384
#define STAGE_BYTES (A_TILE_BYTES + B_TILE_BYTES)   // 32768
#define SM_A(st) (1024 + (st) * STAGE_BYTES)
#define SM_B(st) (SM_A(st) + A_TILE_BYTES)
#define SMEM_BYTES (1024 + NSTAGE * STAGE_BYTES)    // 66560 -> 3 CTAs/SM

// Device scratch, k-chunk-major with SW128 swizzle baked in
__device__ uint8_t g_A[(size_t)KITERS * NI * CHUNKB];   // 8.4 MB
__device__ uint8_t g_B[(size_t)KITERS * NC * CHUNKB];   // 2.1 MB
__device__ float g_csum[NC];                            // sum over d<128
__device__ float g_score[NI];

// ---------------------------------------------------------------- helpers
__device__ __forceinline__ uint32_t smem_u32(const void* p) {
    uint32_t a;
    asm("{ .reg .u64 t; cvta.to.shared.u64 t, %1; cvt.u32.u64 %0, t; }" : "=r"(a) : "l"(p));
    return a;
}
#define MBAR_INIT(a, n) \
    asm volatile("mbarrier.init.shared.b64 [%0], %1;" :: "r"(a), "r"(n) : "memory")
#define MBAR_EXPECT_TX(a, bytes) \
    asm volatile("mbarrier.arrive.expect_tx.shared.b64 _, [%0], %1;" :: "r"(a), "r"(bytes) : "memory")
#define MBAR_WAIT(a, ph) do {                                                     \
    uint32_t _m = (a), _p = (ph), _d;                                             \
    asm volatile("{ .reg .pred p; mbarrier.try_wait.parity.acquire.cta.shared::cta.b64 p, [%1], %2; selp.b32 %0,1,0,p; }" \
                 : "=r"(_d) : "r"(_m), "r"(_p) : "memory");                       \
    if (!_d) {                                                                    \
        asm volatile("{ .reg .pred P; W%=: mbarrier.try_wait.parity.acquire.cta.shared::cta.b64 P, [%0], %1, 0x989680; @P bra.uni D%=; bra.uni W%=; D%=: }" \
                     :: "r"(_m), "r"(_p) : "memory");                             \
    } } while (0)
#define CP_BULK(dst, src, bytes, mbar) \
    asm volatile("cp.async.bulk.shared::cluster.global.mbarrier::complete_tx::bytes " \
                 "[%0], [%1], %2, [%3];" \
                 :: "r"(dst), "l"(src), "r"(bytes), "r"(mbar) : "memory")

__device__ __forceinline__ void ldm_x4(uint32_t* r, uint32_t addr) {
    asm volatile("ldmatrix.sync.aligned.m8n8.x4.shared.b16 {%0,%1,%2,%3}, [%4];"
                 : "=r"(r[0]), "=r"(r[1]), "=r"(r[2]), "=r"(r[3]) : "r"(addr));
}
__device__ __forceinline__ void mma_f16acc(uint32_t* c, const uint32_t* a, const uint32_t* b) {
    asm volatile(
        "mma.sync.aligned.m16n8k16.row.col.f16.f16.f16.f16 "
        "{%0,%1}, {%2,%3,%4,%5}, {%6,%7}, {%0,%1};"
        : "+r"(c[0]), "+r"(c[1])
        : "r"(a[0]), "r"(a[1]), "r"(a[2]), "r"(a[3]), "r"(b[0]), "r"(b[1]));
}

// ---------------------------------------------------------------- prep kernels
__global__ void prep_A_kernel(const float* __restrict__ x) {
    int idx = blockIdx.x * blockDim.x + threadIdx.x;
    if (idx >= NI * KD) return;
    if (idx < NI) g_score[idx] = 0.f;        // fold score zeroing in
    int n = idx >> 7;            // / 128
    int d = idx & (KD - 1);
    float v = x[n * ND + d];
    uint32_t sw = ((uint32_t)(n & 7)) << 4;
    int kch = d >> 6, e = d & 63;            // kch 0..1
    *(__half*)(g_A + ((size_t)kch * NI + n) * CHUNKB + ((2 * e) ^ sw)) =
        __float2half(v * v);
    *(__half*)(g_A + ((size_t)(2 + kch) * NI + n) * CHUNKB + ((2 * e) ^ sw)) =
        __float2half(v);
}

__global__ void prep_B_kernel(const float* __restrict__ centers,
                              const float* __restrict__ sigmas) {
    int warp = (blockIdx.x * blockDim.x + threadIdx.x) >> 5;
    int lane = threadIdx.x & 31;
    if (warp >= NC) return;
    int c = warp;
    uint32_t sw = ((uint32_t)(c & 7)) << 4;
    float acc = 0.f;
    #pragma unroll
    for (int d = lane; d < KD; d += 32) {
        float s   = sigmas[c * ND + d];
        float ce  = centers[c * ND + d];
        float inv = 1.0f / (2.0f * s * s);
        int kch = d >> 6, e = d & 63;
        *(__half*)(g_B + ((size_t)kch * NC + c) * CHUNKB + ((2 * e) ^ sw)) =
            __float2half(inv);
        *(__half*)(g_B + ((size_t)(2 + kch) * NC + c) * CHUNKB + ((2 * e) ^ sw)) =
            __float2half(-2.0f * ce * inv);
        acc = fmaf(ce * ce, inv, acc);
    }
    #pragma unroll
    for (int m = 16; m; m >>= 1) acc += __shfl_xor_sync(0xffffffffu, acc, m);
    if (lane == 0) g_csum[c] = acc;
}

// ---------------------------------------------------------------- main kernel
__global__ void __launch_bounds__(256, 3)
rbf_mma_kernel(const float* __restrict__ x,
               const float* __restrict__ centers,
               const float* __restrict__ sigmas,
               const float* __restrict__ w_lin) {
    extern __shared__ char smem[];
    const uint32_t smem_base = smem_u32(smem);
    const int tid  = threadIdx.x;
    const int lane = tid & 31;
    const int wid  = tid >> 5;
    const int wm   = wid >> 2;      // 0..1  (M)
    const int wn   = wid & 3;       // 0..3  (N)
    const int bn   = blockIdx.x;    // center tile
    const int bm   = blockIdx.y;    // input tile

    if (tid == 0) {
        MBAR_INIT(smem_base + 0, 1);
        MBAR_INIT(smem_base + 8, 1);
    }
    __syncthreads();

    auto issue_stage = [&](int st, int kiter) {
        uint32_t mb = smem_base + st * 8;
        MBAR_EXPECT_TX(mb, STAGE_BYTES);
        const uint8_t* srcA = g_A + ((size_t)kiter * NI + bm * BM) * CHUNKB;
        const uint8_t* srcB = g_B + ((size_t)kiter * NC + bn * BN) * CHUNKB;
        CP_BULK(smem_base + SM_A(st), (const void*)srcA, A_TILE_BYTES, mb);
        CP_BULK(smem_base + SM_B(st), (const void*)srcB, B_TILE_BYTES, mb);
    };

    if (tid == 0) {
        issue_stage(0, 0);
        issue_stage(1, 1);
    }

    // fp16 accumulators: 2 regs per m16n8 tile -> 32 regs
    uint32_t acc[4][4][2];
    #pragma unroll
    for (int mt = 0; mt < 4; mt++)
        #pragma unroll
        for (int nt = 0; nt < 4; nt++) { acc[mt][nt][0] = 0u; acc[mt][nt][1] = 0u; }

    #pragma unroll 1
    for (int k = 0; k < KITERS; k++) {
        const int st = k & 1;
        MBAR_WAIT(smem_base + st * 8, (k >> 1) & 1);

        const uint32_t aBase = smem_base + SM_A(st);
        const uint32_t bBase = smem_base + SM_B(st);
        #pragma unroll
        for (int kc = 0; kc < 4; kc++) {           // 4 x k16 per stage
            uint32_t a[4][4], b[4][2];
            #pragma unroll
            for (int mt = 0; mt < 4; mt++) {
                int row = wm * 64 + mt * 16 + (lane & 15);
                uint32_t boff = kc * 32 + ((lane >> 4) << 4);
                uint32_t addr = aBase + row * CHUNKB + (boff ^ ((row & 7) << 4));
                ldm_x4(a[mt], addr);
            }
            #pragma unroll
            for (int p = 0; p < 2; p++) {
                int g = lane >> 3;            // 0..3: {t0 k0, t0 k8, t1 k0, t1 k8}
                int trow = wn * 32 + p * 16 + (g >> 1) * 8 + (lane & 7);
                uint32_t boff = kc * 32 + ((g & 1) << 4);
                uint32_t addr = bBase + trow * CHUNKB + (boff ^ ((trow & 7) << 4));
                uint32_t bp[4];
                ldm_x4(bp, addr);
                b[2 * p][0] = bp[0]; b[2 * p][1] = bp[1];
                b[2 * p + 1][0] = bp[2]; b[2 * p + 1][1] = bp[3];
            }
            #pragma unroll
            for (int mt = 0; mt < 4; mt++)
                #pragma unroll
                for (int nt = 0; nt < 4; nt++)
                    mma_f16acc(acc[mt][nt], a[mt], b[nt]);
        }

        __syncthreads();
        if (tid == 0 && k + NSTAGE < KITERS) issue_stage(st, k + NSTAGE);
    }

    // ---------------- epilogue: p = partial d2 over 128 dims (lower bound).
    // Skip if p >= TSCREEN; else compute remaining 128 dims exactly (fp32).
    const int cBase = bn * BN + wn * 32;
    float cs[4][2];
    #pragma unroll
    for (int nt = 0; nt < 4; nt++)
        #pragma unroll
        for (int j = 0; j < 2; j++)
            cs[nt][j] = __ldg(&g_csum[cBase + nt * 8 + (lane & 3) * 2 + j]);

    float mn = 1e30f;
    #pragma unroll
    for (int mt = 0; mt < 4; mt++)
        #pragma unroll
        for (int nt = 0; nt < 4; nt++)
            #pragma unroll
            for (int h = 0; h < 2; h++) {
                __half2 hv = *reinterpret_cast<__half2*>(&acc[mt][nt][h]);
                mn = fminf(mn, __low2float(hv)  + cs[nt][0]);
                mn = fminf(mn, __high2float(hv) + cs[nt][1]);
            }

    if (__any_sync(0xffffffffu, mn < TSCREEN)) {    // ~3% of warps
        float rs[4][2];
        #pragma unroll
        for (int mt = 0; mt < 4; mt++) { rs[mt][0] = 0.f; rs[mt][1] = 0.f; }
        #pragma unroll 1
        for (int mt = 0; mt < 4; mt++)
            #pragma unroll 1
            for (int nt = 0; nt < 4; nt++)
                #pragma unroll 1
                for (int h = 0; h < 2; h++) {
                    __half2 hv = *reinterpret_cast<__half2*>(&acc[mt][nt][h]);
                    float pv[2] = { __low2float(hv)  + cs[nt][0],
                                    __high2float(hv) + cs[nt][1] };
                    #pragma unroll 1
                    for (int j = 0; j < 2; j++) {
                        if (pv[j] < TSCREEN) {
                            int row = bm * BM + wm * 64 + mt * 16 + h * 8 + (lane >> 2);
                            int col = cBase + nt * 8 + (lane & 3) * 2 + j;
                            float rest = 0.f;
                            #pragma unroll 4
                            for (int d = KD; d < ND; d++) {
                                float xv = x[row * ND + d];
                                float cv = centers[col * ND + d];
                                float sv = sigmas[col * ND + d];
                                float df = xv - cv;
                                rest += (df * df) / (2.0f * sv * sv);
                            }
                            float d2 = pv[j] + rest;
                            if (d2 < 60.f)
                                rs[mt][h] = fmaf(expf(-d2), __ldg(&w_lin[col]), rs[mt][h]);
                        }
                    }
                }
        #pragma unroll
        for (int mt = 0; mt < 4; mt++)
            #pragma unroll
            for (int h = 0; h < 2; h++) {
                float v = rs[mt][h];
                v += __shfl_xor_sync(0xffffffffu, v, 1);
                v += __shfl_xor_sync(0xffffffffu, v, 2);
                if ((lane & 3) == 0)
                    atomicAdd(&g_score[bm * BM + wm * 64 + mt * 16 + h * 8 + (lane >> 2)], v);
            }
    }
    // fast path: skipped mass bounded; g_score pre-zeroed
}

__global__ void finalize_kernel(const float* __restrict__ b_lin,
                                float* __restrict__ out) {
    int n = blockIdx.x * blockDim.x + threadIdx.x;
    if (n < NI) {
        float s = g_score[n] + b_lin[0];
        out[n] = 1.0f / (1.0f + __expf(-s));
    }
}

// ---------------------------------------------------------------- launch
extern "C" void kernel_launch(void* const* d_in, const int* in_sizes, int n_in,
                              void* d_out, int out_size) {
    const float* x       = (const float*)d_in[0];
    const float* centers = (const float*)d_in[1];
    const float* sigmas  = (const float*)d_in[2];
    const float* w_lin   = (const float*)d_in[3];
    const float* b_lin   = (const float*)d_in[4];
    float* out = (float*)d_out;

    cudaFuncSetAttribute(rbf_mma_kernel,
                         cudaFuncAttributeMaxDynamicSharedMemorySize, SMEM_BYTES);

    prep_A_kernel<<<(NI * KD + 255) / 256, 256>>>(x);
    prep_B_kernel<<<(NC * 32 + 255) / 256, 256>>>(centers, sigmas);
    dim3 grid(NC / BN, NI / BM);   // (32, 128)
    rbf_mma_kernel<<<grid, 256, SMEM_BYTES>>>(x, centers, sigmas, w_lin);
    finalize_kernel<<<NI / 256, 256>>>(b_lin, out);
}